// round 2
// baseline (speedup 1.0000x reference)
#include <cuda_runtime.h>
#include <cuda_bf16.h>

#define B_  4096
#define S_  200
#define D_  64
#define NT  256

// -------- shared memory layout (floats, all float4-aligned) --------
#define OFF_EMB   0                    // 200*64 = 12800
#define OFF_SATT  12800                // 200*8  = 1600  (stride-8 padded scores/exp)
#define OFF_AW    14400                // 320
#define OFF_AB    14720                // 8
#define OFF_WC    14728                // 18*64 = 1152
#define OFF_ROWS  15880                // 200 ints
#define OFF_PART  16080                // 8 warps * 320 = 2560
#define OFF_UREP  18640                // 320
#define OFF_SINV  18960                // 8
#define OFF_Z     18968                // 24
#define OFF_LG    18992                // 8
#define SMEM_FLOATS 19000              // 76000 bytes -> 3 CTAs/SM

__device__ float        g_loss[B_];
__device__ unsigned int g_cnt = 0u;

__global__ void __launch_bounds__(NT)
tan_kernel(const int* __restrict__ x, const float* __restrict__ y,
           const float* __restrict__ emb_table,
           const float* __restrict__ att_w, const float* __restrict__ att_b,
           const float* __restrict__ W0, const float* __restrict__ W1,
           const float* __restrict__ W2, const float* __restrict__ W3,
           const float* __restrict__ W4,
           float* __restrict__ out)
{
    extern __shared__ float sm[];
    float* emb   = sm + OFF_EMB;
    float* satt8 = sm + OFF_SATT;
    float* aw    = sm + OFF_AW;
    float* ab    = sm + OFF_AB;
    float* Wc    = sm + OFF_WC;
    int*   rows  = (int*)(sm + OFF_ROWS);
    float* part  = sm + OFF_PART;
    float* urep  = sm + OFF_UREP;
    float* sinv  = sm + OFF_SINV;
    float* zb    = sm + OFF_Z;
    float* lg    = sm + OFF_LG;

    const int tid  = threadIdx.x;
    const int b    = blockIdx.x;
    const int warp = tid >> 5, lane = tid & 31;
    const int q    = tid & 15;          // 16-lane subgroup position (column tile)

    // ---- Phase A: stage small weights + gather indices ----
    for (int i = tid; i < 320; i += NT) aw[i] = att_w[i];
    if (tid < 5) ab[tid] = att_b[tid];
    for (int i = tid; i < 128; i += NT) Wc[i]       = W0[i];
    for (int i = tid; i < 256; i += NT) Wc[128 + i] = W1[i];
    for (int i = tid; i < 256; i += NT) Wc[384 + i] = W2[i];
    for (int i = tid; i < 128; i += NT) Wc[640 + i] = W3[i];
    for (int i = tid; i < 384; i += NT) Wc[768 + i] = W4[i];
    for (int s = tid; s < S_; s += NT)  rows[s] = x[b * S_ + s];
    __syncthreads();

    // ---- Phase B: gather rows AND compute attention logits in one pass ----
    // 16 threads per row; each holds 4 columns, butterfly-reduces 5 dot products.
#pragma unroll 1
    for (int i = 0; i < 13; i++) {
        const int idx   = i * NT + tid;
        const int s_raw = idx >> 4;
        const int s     = (s_raw < S_) ? s_raw : (S_ - 1);   // clamp: full-warp shuffles
        const float4 v  = __ldg((const float4*)(emb_table + (long)rows[s] * D_ + q * 4));
        *(float4*)(emb + s * D_ + q * 4) = v;                // duplicate rows write same data

        const float4 w0 = *(const float4*)(aw +          q * 4);
        const float4 w1 = *(const float4*)(aw +  64    + q * 4);
        const float4 w2 = *(const float4*)(aw + 128    + q * 4);
        const float4 w3 = *(const float4*)(aw + 192    + q * 4);
        const float4 w4 = *(const float4*)(aw + 256    + q * 4);
        float a0 = v.x*w0.x + v.y*w0.y + v.z*w0.z + v.w*w0.w;
        float a1 = v.x*w1.x + v.y*w1.y + v.z*w1.z + v.w*w1.w;
        float a2 = v.x*w2.x + v.y*w2.y + v.z*w2.z + v.w*w2.w;
        float a3 = v.x*w3.x + v.y*w3.y + v.z*w3.z + v.w*w3.w;
        float a4 = v.x*w4.x + v.y*w4.y + v.z*w4.z + v.w*w4.w;
#pragma unroll
        for (int o = 1; o < 16; o <<= 1) {
            a0 += __shfl_xor_sync(0xffffffffu, a0, o);
            a1 += __shfl_xor_sync(0xffffffffu, a1, o);
            a2 += __shfl_xor_sync(0xffffffffu, a2, o);
            a3 += __shfl_xor_sync(0xffffffffu, a3, o);
            a4 += __shfl_xor_sync(0xffffffffu, a4, o);
        }
        if (q < 5 && s_raw < S_) {
            const float av = (q == 0) ? a0 : (q == 1) ? a1 : (q == 2) ? a2
                           : (q == 3) ? a3 : a4;
            satt8[s * 8 + q] = tanhf(av + ab[q]);
        }
    }
    __syncthreads();

    // ---- Phase D: softmax over S per head k (one warp per k), keep exp unnormalized ----
    if (warp < 5) {
        const int k = warp;
        float m = -1e30f;
        for (int s = lane; s < S_; s += 32) m = fmaxf(m, satt8[s * 8 + k]);
#pragma unroll
        for (int o = 16; o; o >>= 1) m = fmaxf(m, __shfl_xor_sync(0xffffffffu, m, o));
        float sum = 0.f;
        for (int s = lane; s < S_; s += 32) {
            const float e = __expf(satt8[s * 8 + k] - m);
            satt8[s * 8 + k] = e;
            sum += e;
        }
#pragma unroll
        for (int o = 16; o; o >>= 1) sum += __shfl_xor_sync(0xffffffffu, sum, o);
        if (lane == 0) sinv[k] = 1.0f / sum;
    }
    __syncthreads();

    // ---- Phase E: user_rep[k][d] = sum_s emb[s][d]*score[s][k], vectorized ----
    // 16 groups of 16 threads; group g handles s = g, g+16, ...; thread owns d = 4q..4q+3.
    {
        const int g = tid >> 4;
        float4 c0 = {0,0,0,0}, c1 = {0,0,0,0}, c2 = {0,0,0,0}, c3 = {0,0,0,0}, c4 = {0,0,0,0};
        for (int s = g; s < S_; s += 16) {
            const float4 e  = *(const float4*)(emb + s * D_ + q * 4);
            const float4 sc = *(const float4*)(satt8 + s * 8);
            const float  s4 = satt8[s * 8 + 4];
            c0.x += e.x*sc.x; c0.y += e.y*sc.x; c0.z += e.z*sc.x; c0.w += e.w*sc.x;
            c1.x += e.x*sc.y; c1.y += e.y*sc.y; c1.z += e.z*sc.y; c1.w += e.w*sc.y;
            c2.x += e.x*sc.z; c2.y += e.y*sc.z; c2.z += e.z*sc.z; c2.w += e.w*sc.z;
            c3.x += e.x*sc.w; c3.y += e.y*sc.w; c3.z += e.z*sc.w; c3.w += e.w*sc.w;
            c4.x += e.x*s4;   c4.y += e.y*s4;   c4.z += e.z*s4;   c4.w += e.w*s4;
        }
        // combine the two 16-groups within each warp
#define RED16(v) v.x += __shfl_xor_sync(0xffffffffu, v.x, 16); \
                 v.y += __shfl_xor_sync(0xffffffffu, v.y, 16); \
                 v.z += __shfl_xor_sync(0xffffffffu, v.z, 16); \
                 v.w += __shfl_xor_sync(0xffffffffu, v.w, 16);
        RED16(c0) RED16(c1) RED16(c2) RED16(c3) RED16(c4)
        if (lane < 16) {
            float* pp = part + warp * 320;
            *(float4*)(pp +        q * 4) = c0;
            *(float4*)(pp +  64 +  q * 4) = c1;
            *(float4*)(pp + 128 +  q * 4) = c2;
            *(float4*)(pp + 192 +  q * 4) = c3;
            *(float4*)(pp + 256 +  q * 4) = c4;
        }
    }
    __syncthreads();
    for (int j = tid; j < 320; j += NT) {
        float v = 0.f;
#pragma unroll
        for (int w = 0; w < 8; w++) v += part[w * 320 + j];
        urep[j] = v * sinv[j >> 6];
    }
    __syncthreads();

    // ---- Phase F: 18 logits ----
    if (tid < 18) {
        const int j = tid;
        const int g = (j < 2) ? 0 : (j < 6) ? 1 : (j < 10) ? 2 : (j < 12) ? 3 : 4;
        const float* w = Wc + j * 64;
        const float* u = urep + g * 64;
        float z = 0.f;
#pragma unroll
        for (int i = 0; i < 16; i++) {
            const float4 uv = *(const float4*)(u + i * 4);
            const float4 wv = *(const float4*)(w + i * 4);
            z += uv.x*wv.x + uv.y*wv.y + uv.z*wv.z + uv.w*wv.w;
        }
        zb[j] = z;
    }
    __syncthreads();
    if (tid < 5) {
        const int cum[6] = {0, 2, 6, 10, 12, 18};
        const int g = tid, c0 = cum[g], n = cum[g + 1] - c0;
        float m = -1e30f;
        for (int j = 0; j < n; j++) m = fmaxf(m, zb[c0 + j]);
        float sum = 0.f;
        for (int j = 0; j < n; j++) sum += __expf(zb[c0 + j] - m);
        const float inv = 1.0f / sum;
        const float lse = m + __logf(sum);
        float lo = 0.f;
        for (int j = 0; j < n; j++) {
            const float zv = zb[c0 + j];
            out[b * 18 + c0 + j] = __expf(zv - m) * inv;
            lo -= y[b * 18 + c0 + j] * (zv - lse);   // y is one-hot
        }
        lg[g] = lo;
    }
    __syncthreads();

    // ---- Loss: per-b partial, then last-CTA deterministic tree reduce ----
    __shared__ float red[NT];
    __shared__ int   isLast;
    if (tid == 0) {
        g_loss[b] = lg[0] + lg[1] + lg[2] + lg[3] + lg[4];
        __threadfence();
        const unsigned old = atomicAdd(&g_cnt, 1u);
        isLast = (old == (unsigned)(B_ - 1));
    }
    __syncthreads();
    if (isLast) {
        float s = 0.f;
        for (int i = tid; i < B_; i += NT) s += g_loss[i];
        red[tid] = s;
        __syncthreads();
        for (int o = NT / 2; o; o >>= 1) {
            if (tid < o) red[tid] += red[tid + o];
            __syncthreads();
        }
        if (tid == 0) {
            out[B_ * 18] = red[0] * (1.0f / B_);
            g_cnt = 0u;                       // reset for next graph replay
        }
    }
}

extern "C" void kernel_launch(void* const* d_in, const int* in_sizes, int n_in,
                              void* d_out, int out_size)
{
    const int*   x   = (const int*)  d_in[0];
    const float* y   = (const float*)d_in[1];
    const float* emb = (const float*)d_in[2];
    const float* aw  = (const float*)d_in[3];
    const float* ab  = (const float*)d_in[4];
    const float* W0  = (const float*)d_in[5];
    const float* W1  = (const float*)d_in[6];
    const float* W2  = (const float*)d_in[7];
    const float* W3  = (const float*)d_in[8];
    const float* W4  = (const float*)d_in[9];
    float* out = (float*)d_out;

    const size_t smem = SMEM_FLOATS * sizeof(float);
    cudaFuncSetAttribute(tan_kernel, cudaFuncAttributeMaxDynamicSharedMemorySize, (int)smem);
    tan_kernel<<<B_, NT, smem>>>(x, y, emb, aw, ab, W0, W1, W2, W3, W4, out);
}

// round 7
// speedup vs baseline: 2.6875x; 2.6875x over previous
#include <cuda_runtime.h>
#include <cuda_fp16.h>

#define B_  4096
#define S_  200
#define NT  256

__constant__ float c_aw[320];
__constant__ float c_ab[8];

__device__ float        g_loss[B_];
__device__ unsigned int g_cnt = 0u;

// -------- shared memory layout (bytes) --------
#define SM_EMB   0        // half[200*66]  = 26400  (stride 66 halves: conflict-free rows+cols)
#define SM_SATT  26400    // float[5*200]  = 4000   (transposed scores)
#define SM_ROWS  30400    // int[200]      = 800
#define SM_PART  31200    // float[8*320]  = 10240
#define SM_UREP  41440    // float[320]    = 1280
#define SM_SINV  42720    // float[8]      = 32
#define SM_Z     42752    // float[24]     = 96
#define SM_LG    42848    // float[8]      = 32
#define SM_BYTES 42880    // -> 5 CTAs/SM

__global__ void __launch_bounds__(NT, 5)
tan_kernel(const int* __restrict__ x, const float* __restrict__ y,
           const float* __restrict__ emb_table,
           const float* __restrict__ W0, const float* __restrict__ W1,
           const float* __restrict__ W2, const float* __restrict__ W3,
           const float* __restrict__ W4,
           float* __restrict__ out)
{
    extern __shared__ char smraw[];
    half*  embh = (half*) (smraw + SM_EMB);
    float* satt = (float*)(smraw + SM_SATT);
    int*   rows = (int*)  (smraw + SM_ROWS);
    float* part = (float*)(smraw + SM_PART);
    float* urep = (float*)(smraw + SM_UREP);
    float* sinv = (float*)(smraw + SM_SINV);
    float* zb   = (float*)(smraw + SM_Z);
    float* lg   = (float*)(smraw + SM_LG);

    const int tid  = threadIdx.x;
    const int b    = blockIdx.x;
    const int warp = tid >> 5, lane = tid & 31;

    // ---- Phase A: gather indices ----
    for (int s = tid; s < S_; s += NT) rows[s] = x[b * S_ + s];
    __syncthreads();

    // ---- Phase B: gather 200 rows (float4), convert to half2, stage in SMEM ----
#pragma unroll 4
    for (int i = 0; i < 13; i++) {
        const int idx = i * NT + tid;
        if (idx < S_ * 16) {
            const int s = idx >> 4, q = idx & 15;
            const float4 v = __ldg((const float4*)(emb_table + (size_t)rows[s] * 64 + q * 4));
            *(half2*)(embh + s * 66 + q * 4)     = __floats2half2_rn(v.x, v.y);
            *(half2*)(embh + s * 66 + q * 4 + 2) = __floats2half2_rn(v.z, v.w);
        }
    }
    __syncthreads();

    // ---- Phase C: attention logits + tanh (one thread per s; weights from constant) ----
    if (tid < S_) {
        const int s = tid;
        const half2* e2 = (const half2*)(embh + s * 66);
        float a0 = c_ab[0], a1 = c_ab[1], a2 = c_ab[2], a3 = c_ab[3], a4 = c_ab[4];
#pragma unroll
        for (int j = 0; j < 32; j++) {
            const float2 e = __half22float2(e2[j]);
            a0 += e.x * c_aw[      2*j] + e.y * c_aw[      2*j + 1];
            a1 += e.x * c_aw[ 64 + 2*j] + e.y * c_aw[ 64 + 2*j + 1];
            a2 += e.x * c_aw[128 + 2*j] + e.y * c_aw[128 + 2*j + 1];
            a3 += e.x * c_aw[192 + 2*j] + e.y * c_aw[192 + 2*j + 1];
            a4 += e.x * c_aw[256 + 2*j] + e.y * c_aw[256 + 2*j + 1];
        }
        satt[      s] = tanhf(a0);
        satt[200 + s] = tanhf(a1);
        satt[400 + s] = tanhf(a2);
        satt[600 + s] = tanhf(a3);
        satt[800 + s] = tanhf(a4);
    }
    __syncthreads();

    // ---- Phase D: softmax over S per head (one warp per k; row access, conflict-free) ----
    if (warp < 5) {
        float* row = satt + warp * 200;
        float m = -1e30f;
        for (int s = lane; s < S_; s += 32) m = fmaxf(m, row[s]);
#pragma unroll
        for (int o = 16; o; o >>= 1) m = fmaxf(m, __shfl_xor_sync(0xffffffffu, m, o));
        float sum = 0.f;
        for (int s = lane; s < S_; s += 32) {
            const float e = __expf(row[s] - m);
            row[s] = e;                       // unnormalized; fold 1/sum later
            sum += e;
        }
#pragma unroll
        for (int o = 16; o; o >>= 1) sum += __shfl_xor_sync(0xffffffffu, sum, o);
        if (lane == 0) sinv[warp] = 1.0f / sum;
    }
    __syncthreads();

    // ---- Phase E: user_rep[k][d] = sum_s emb[s][d]*score[s][k] ----
    // warp w handles s = w, w+8, ...; lane owns dims [2*lane, 2*lane+1] (one half2).
    {
        float2 a0 = {0,0}, a1 = {0,0}, a2 = {0,0}, a3 = {0,0}, a4 = {0,0};
        for (int s = warp; s < S_; s += 8) {
            const float2 e = __half22float2(*(const half2*)(embh + s * 66 + 2 * lane));
            const float s0 = satt[s],       s1 = satt[200 + s], s2 = satt[400 + s];
            const float s3 = satt[600 + s], s4 = satt[800 + s];
            a0.x += e.x * s0; a0.y += e.y * s0;
            a1.x += e.x * s1; a1.y += e.y * s1;
            a2.x += e.x * s2; a2.y += e.y * s2;
            a3.x += e.x * s3; a3.y += e.y * s3;
            a4.x += e.x * s4; a4.y += e.y * s4;
        }
        float* pp = part + warp * 320 + 2 * lane;
        *(float2*)(pp      ) = a0;
        *(float2*)(pp +  64) = a1;
        *(float2*)(pp + 128) = a2;
        *(float2*)(pp + 192) = a3;
        *(float2*)(pp + 256) = a4;
    }
    __syncthreads();
    for (int j = tid; j < 320; j += NT) {
        float v = 0.f;
#pragma unroll
        for (int w = 0; w < 8; w++) v += part[w * 320 + j];
        urep[j] = v * sinv[j >> 6];
    }
    __syncthreads();

    // ---- Phase F: 18 logits (weights straight from global; hot in L1/L2) ----
    if (tid < 18) {
        const int j = tid;
        const float* wp = (j < 2)  ? (W0 + j * 64)
                        : (j < 6)  ? (W1 + (j - 2)  * 64)
                        : (j < 10) ? (W2 + (j - 6)  * 64)
                        : (j < 12) ? (W3 + (j - 10) * 64)
                                   : (W4 + (j - 12) * 64);
        const int g = (j < 2) ? 0 : (j < 6) ? 1 : (j < 10) ? 2 : (j < 12) ? 3 : 4;
        const float* u = urep + g * 64;
        float z = 0.f;
#pragma unroll
        for (int i = 0; i < 16; i++) {
            const float4 uv = *(const float4*)(u + i * 4);
            const float4 wv = __ldg((const float4*)(wp + i * 4));
            z += uv.x*wv.x + uv.y*wv.y + uv.z*wv.z + uv.w*wv.w;
        }
        zb[j] = z;
    }
    __syncthreads();

    // ---- Phase G: per-group softmax + loss ----
    if (tid < 5) {
        const int cum[6] = {0, 2, 6, 10, 12, 18};
        const int g = tid, c0 = cum[g], n = cum[g + 1] - c0;
        float m = -1e30f;
        for (int j = 0; j < n; j++) m = fmaxf(m, zb[c0 + j]);
        float sum = 0.f;
        for (int j = 0; j < n; j++) sum += __expf(zb[c0 + j] - m);
        const float inv = 1.0f / sum;
        const float lse = m + __logf(sum);
        float lo = 0.f;
        for (int j = 0; j < n; j++) {
            const float zv = zb[c0 + j];
            out[b * 18 + c0 + j] = __expf(zv - m) * inv;
            lo -= y[b * 18 + c0 + j] * (zv - lse);   // y is one-hot
        }
        lg[g] = lo;
    }
    __syncthreads();

    // ---- Loss epilogue: last-CTA deterministic tree reduce ----
    __shared__ float red[NT];
    __shared__ int   isLast;
    if (tid == 0) {
        g_loss[b] = lg[0] + lg[1] + lg[2] + lg[3] + lg[4];
        __threadfence();
        const unsigned old = atomicAdd(&g_cnt, 1u);
        isLast = (old == (unsigned)(B_ - 1));
    }
    __syncthreads();
    if (isLast) {
        float s = 0.f;
        for (int i = tid; i < B_; i += NT) s += g_loss[i];
        red[tid] = s;
        __syncthreads();
        for (int o = NT / 2; o; o >>= 1) {
            if (tid < o) red[tid] += red[tid + o];
            __syncthreads();
        }
        if (tid == 0) {
            out[B_ * 18] = red[0] * (1.0f / B_);
            g_cnt = 0u;                       // reset for next graph replay
        }
    }
}

extern "C" void kernel_launch(void* const* d_in, const int* in_sizes, int n_in,
                              void* d_out, int out_size)
{
    const int*   x   = (const int*)  d_in[0];
    const float* y   = (const float*)d_in[1];
    const float* emb = (const float*)d_in[2];
    const float* aw  = (const float*)d_in[3];
    const float* ab  = (const float*)d_in[4];
    const float* W0  = (const float*)d_in[5];
    const float* W1  = (const float*)d_in[6];
    const float* W2  = (const float*)d_in[7];
    const float* W3  = (const float*)d_in[8];
    const float* W4  = (const float*)d_in[9];
    float* out = (float*)d_out;

    // Graph-capturable D2D memcpys into constant memory
    cudaMemcpyToSymbolAsync(c_aw, aw, 320 * sizeof(float), 0, cudaMemcpyDeviceToDevice, 0);
    cudaMemcpyToSymbolAsync(c_ab, ab, 5   * sizeof(float), 0, cudaMemcpyDeviceToDevice, 0);

    tan_kernel<<<B_, NT, SM_BYTES>>>(x, y, emb, W0, W1, W2, W3, W4, out);
}

// round 9
// speedup vs baseline: 2.7472x; 1.0222x over previous
#include <cuda_runtime.h>
#include <cuda_fp16.h>

#define B_  4096
#define S_  200
#define NT  256

__device__ float        g_loss[B_];
__device__ unsigned int g_cnt = 0u;

// -------- shared memory layout (bytes) --------
#define SM_EMB   0        // half[200*66] = 26400 (stride 66 halves: conflict-free rows+cols)
#define SM_SATT  26400    // float[5*200] = 4000  (transposed scores; later reused as urep)
#define SM_AW    30400    // float[320]   = 1280  (att_w, float4-aligned)
#define SM_AB    31680    // float[8]     = 32
#define SM_ROWS  31712    // int[200]     = 800
#define SM_PART  32512    // half[8*320]  = 5120  (also reused as float red[256] in epilogue)
#define SM_SINV  37632    // float[8]     = 32
#define SM_Z     37664    // float[24]    = 96
#define SM_LG    37760    // float[8]     = 32
#define SM_BYTES 37792    // 6 CTAs/SM (37792*6 = 226.8KB <= 228KB)

__global__ void __launch_bounds__(NT, 6)
tan_kernel(const int* __restrict__ x, const float* __restrict__ y,
           const float* __restrict__ emb_table,
           const float* __restrict__ att_w, const float* __restrict__ att_b,
           const float* __restrict__ W0, const float* __restrict__ W1,
           const float* __restrict__ W2, const float* __restrict__ W3,
           const float* __restrict__ W4,
           float* __restrict__ out)
{
    extern __shared__ char smraw[];
    half*  embh  = (half*) (smraw + SM_EMB);
    float* satt  = (float*)(smraw + SM_SATT);
    float* aw    = (float*)(smraw + SM_AW);
    float* ab    = (float*)(smraw + SM_AB);
    int*   rows  = (int*)  (smraw + SM_ROWS);
    half*  parth = (half*) (smraw + SM_PART);
    float* urep  = (float*)(smraw + SM_SATT);   // overlays satt (dead after Phase E)
    float* red   = (float*)(smraw + SM_PART);   // overlays part (dead after urep)
    float* sinv  = (float*)(smraw + SM_SINV);
    float* zb    = (float*)(smraw + SM_Z);
    float* lg    = (float*)(smraw + SM_LG);

    const int tid  = threadIdx.x;
    const int b    = blockIdx.x;
    const int warp = tid >> 5, lane = tid & 31;

    // ---- Phase A: stage att weights + gather indices ----
    for (int i = tid; i < 320; i += NT) aw[i] = att_w[i];
    if (tid < 5) ab[tid] = att_b[tid];
    for (int s = tid; s < S_; s += NT) rows[s] = x[b * S_ + s];
    __syncthreads();

    // ---- Phase B: gather 200 rows (float4), convert to half2, stage in SMEM ----
#pragma unroll 4
    for (int i = 0; i < 13; i++) {
        const int idx = i * NT + tid;
        if (idx < S_ * 16) {
            const int s = idx >> 4, q = idx & 15;
            const float4 v = __ldg((const float4*)(emb_table + (size_t)rows[s] * 64 + q * 4));
            *(half2*)(embh + s * 66 + q * 4)     = __floats2half2_rn(v.x, v.y);
            *(half2*)(embh + s * 66 + q * 4 + 2) = __floats2half2_rn(v.z, v.w);
        }
    }
    __syncthreads();

    // ---- Phase C: attention logits + tanh (one thread per s; float4 broadcast weights) ----
    if (tid < S_) {
        const int s = tid;
        const half2* e2 = (const half2*)(embh + s * 66);
        float a0 = ab[0], a1 = ab[1], a2 = ab[2], a3 = ab[3], a4 = ab[4];
#pragma unroll
        for (int j = 0; j < 16; j++) {
            const float2 ea = __half22float2(e2[2 * j]);
            const float2 eb = __half22float2(e2[2 * j + 1]);
            const float4 w0 = *(const float4*)(aw +        j * 4);
            const float4 w1 = *(const float4*)(aw +  64 +  j * 4);
            const float4 w2 = *(const float4*)(aw + 128 +  j * 4);
            const float4 w3 = *(const float4*)(aw + 192 +  j * 4);
            const float4 w4 = *(const float4*)(aw + 256 +  j * 4);
            a0 += ea.x*w0.x + ea.y*w0.y + eb.x*w0.z + eb.y*w0.w;
            a1 += ea.x*w1.x + ea.y*w1.y + eb.x*w1.z + eb.y*w1.w;
            a2 += ea.x*w2.x + ea.y*w2.y + eb.x*w2.z + eb.y*w2.w;
            a3 += ea.x*w3.x + ea.y*w3.y + eb.x*w3.z + eb.y*w3.w;
            a4 += ea.x*w4.x + ea.y*w4.y + eb.x*w4.z + eb.y*w4.w;
        }
        satt[      s] = tanhf(a0);
        satt[200 + s] = tanhf(a1);
        satt[400 + s] = tanhf(a2);
        satt[600 + s] = tanhf(a3);
        satt[800 + s] = tanhf(a4);
    }
    __syncthreads();

    // ---- Phase D: softmax over S per head (one warp per k; conflict-free rows) ----
    if (warp < 5) {
        float* row = satt + warp * 200;
        float m = -1e30f;
        for (int s = lane; s < S_; s += 32) m = fmaxf(m, row[s]);
#pragma unroll
        for (int o = 16; o; o >>= 1) m = fmaxf(m, __shfl_xor_sync(0xffffffffu, m, o));
        float sum = 0.f;
        for (int s = lane; s < S_; s += 32) {
            const float e = __expf(row[s] - m);
            row[s] = e;                       // unnormalized; fold 1/sum later
            sum += e;
        }
#pragma unroll
        for (int o = 16; o; o >>= 1) sum += __shfl_xor_sync(0xffffffffu, sum, o);
        if (lane == 0) sinv[warp] = 1.0f / sum;
    }
    __syncthreads();

    // ---- Phase E: user_rep[k][d] partials; warp w does s = w, w+8, ... ----
    {
        float2 a0 = {0,0}, a1 = {0,0}, a2 = {0,0}, a3 = {0,0}, a4 = {0,0};
        for (int s = warp; s < S_; s += 8) {
            const float2 e = __half22float2(*(const half2*)(embh + s * 66 + 2 * lane));
            const float s0 = satt[s],       s1 = satt[200 + s], s2 = satt[400 + s];
            const float s3 = satt[600 + s], s4 = satt[800 + s];
            a0.x += e.x * s0; a0.y += e.y * s0;
            a1.x += e.x * s1; a1.y += e.y * s1;
            a2.x += e.x * s2; a2.y += e.y * s2;
            a3.x += e.x * s3; a3.y += e.y * s3;
            a4.x += e.x * s4; a4.y += e.y * s4;
        }
        half* pp = parth + warp * 320 + 2 * lane;
        *(half2*)(pp      ) = __floats2half2_rn(a0.x, a0.y);
        *(half2*)(pp +  64) = __floats2half2_rn(a1.x, a1.y);
        *(half2*)(pp + 128) = __floats2half2_rn(a2.x, a2.y);
        *(half2*)(pp + 192) = __floats2half2_rn(a3.x, a3.y);
        *(half2*)(pp + 256) = __floats2half2_rn(a4.x, a4.y);
    }
    __syncthreads();
    // combine the 8 warp partials -> urep (overlays satt, which is now dead)
    if (tid < 160) {
        float2 v = {0.f, 0.f};
#pragma unroll
        for (int w = 0; w < 8; w++) {
            const float2 t = __half22float2(*(const half2*)(parth + w * 320 + 2 * tid));
            v.x += t.x; v.y += t.y;
        }
        const float sc = sinv[(2 * tid) >> 6];
        urep[2 * tid]     = v.x * sc;
        urep[2 * tid + 1] = v.y * sc;
    }
    __syncthreads();

    // ---- Phase F: 18 logits ----
    if (tid < 18) {
        const int j = tid;
        const float* wp = (j < 2)  ? (W0 + j * 64)
                        : (j < 6)  ? (W1 + (j - 2)  * 64)
                        : (j < 10) ? (W2 + (j - 6)  * 64)
                        : (j < 12) ? (W3 + (j - 10) * 64)
                                   : (W4 + (j - 12) * 64);
        const int g = (j < 2) ? 0 : (j < 6) ? 1 : (j < 10) ? 2 : (j < 12) ? 3 : 4;
        const float* u = urep + g * 64;
        float z = 0.f;
#pragma unroll
        for (int i = 0; i < 16; i++) {
            const float4 uv = *(const float4*)(u + i * 4);
            const float4 wv = __ldg((const float4*)(wp + i * 4));
            z += uv.x*wv.x + uv.y*wv.y + uv.z*wv.z + uv.w*wv.w;
        }
        zb[j] = z;
    }
    __syncthreads();

    // ---- Phase G: per-group softmax + loss ----
    if (tid < 5) {
        const int cum[6] = {0, 2, 6, 10, 12, 18};
        const int g = tid, c0 = cum[g], n = cum[g + 1] - c0;
        float m = -1e30f;
        for (int j = 0; j < n; j++) m = fmaxf(m, zb[c0 + j]);
        float sum = 0.f;
        for (int j = 0; j < n; j++) sum += __expf(zb[c0 + j] - m);
        const float inv = 1.0f / sum;
        const float lse = m + __logf(sum);
        float lo = 0.f;
        for (int j = 0; j < n; j++) {
            const float zv = zb[c0 + j];
            out[b * 18 + c0 + j] = __expf(zv - m) * inv;
            lo -= y[b * 18 + c0 + j] * (zv - lse);   // y is one-hot
        }
        lg[g] = lo;
    }
    __syncthreads();

    // ---- Loss epilogue: last-CTA deterministic tree reduce (red overlays part) ----
    __shared__ int isLast;
    if (tid == 0) {
        g_loss[b] = lg[0] + lg[1] + lg[2] + lg[3] + lg[4];
        __threadfence();
        const unsigned old = atomicAdd(&g_cnt, 1u);
        isLast = (old == (unsigned)(B_ - 1));
    }
    __syncthreads();
    if (isLast) {
        float s = 0.f;
        for (int i = tid; i < B_; i += NT) s += g_loss[i];
        red[tid] = s;
        __syncthreads();
        for (int o = NT / 2; o; o >>= 1) {
            if (tid < o) red[tid] += red[tid + o];
            __syncthreads();
        }
        if (tid == 0) {
            out[B_ * 18] = red[0] * (1.0f / B_);
            g_cnt = 0u;                       // reset for next graph replay
        }
    }
}

extern "C" void kernel_launch(void* const* d_in, const int* in_sizes, int n_in,
                              void* d_out, int out_size)
{
    const int*   x   = (const int*)  d_in[0];
    const float* y   = (const float*)d_in[1];
    const float* emb = (const float*)d_in[2];
    const float* aw  = (const float*)d_in[3];
    const float* ab  = (const float*)d_in[4];
    const float* W0  = (const float*)d_in[5];
    const float* W1  = (const float*)d_in[6];
    const float* W2  = (const float*)d_in[7];
    const float* W3  = (const float*)d_in[8];
    const float* W4  = (const float*)d_in[9];
    float* out = (float*)d_out;

    static bool attr_set = false;
    if (!attr_set) {
        cudaFuncSetAttribute(tan_kernel, cudaFuncAttributeMaxDynamicSharedMemorySize, SM_BYTES);
        attr_set = true;
    }
    tan_kernel<<<B_, NT, SM_BYTES>>>(x, y, emb, aw, ab, W0, W1, W2, W3, W4, out);
}

// round 10
// speedup vs baseline: 2.7483x; 1.0004x over previous
#include <cuda_runtime.h>
#include <cuda_fp16.h>

#define B_  4096
#define S_  200
#define NT  256

__device__ float        g_loss[B_];
__device__ unsigned int g_cnt = 0u;

// -------- shared memory layout (bytes) --------
#define SM_EMB   0        // half[200*66] = 26400 (stride 66 halves: conflict-free rows+cols)
#define SM_SATT  26400    // float[5*200] = 4000  (transposed scores; urep overlays after E)
#define SM_SC01  30400    // half2[200]   = 800   (packed exp scores, heads 0,1)
#define SM_SC23  31200    // half2[200]   = 800   (heads 2,3)
#define SM_AW    32000    // float[320]   = 1280  (att_w, float4-aligned)
#define SM_AB    33280    // float[8]     = 32
#define SM_PART  33312    // half[4*320] = 2560 ; rows(800B) and red(1024B) overlay here
#define SM_SINV  35872    // float[8]     = 32
#define SM_Z     35904    // float[24]    = 96
#define SM_LG    36000    // float[8]     = 32
#define SM_BYTES 36032    // 6 CTAs/SM (216KB)

__global__ void __launch_bounds__(NT, 6)
tan_kernel(const int* __restrict__ x, const float* __restrict__ y,
           const float* __restrict__ emb_table,
           const float* __restrict__ att_w, const float* __restrict__ att_b,
           const float* __restrict__ W0, const float* __restrict__ W1,
           const float* __restrict__ W2, const float* __restrict__ W3,
           const float* __restrict__ W4,
           float* __restrict__ out)
{
    extern __shared__ char smraw[];
    half*  embh  = (half*) (smraw + SM_EMB);
    float* satt  = (float*)(smraw + SM_SATT);
    half2* sc01  = (half2*)(smraw + SM_SC01);
    half2* sc23  = (half2*)(smraw + SM_SC23);
    float* aw    = (float*)(smraw + SM_AW);
    float* ab    = (float*)(smraw + SM_AB);
    half*  parth = (half*) (smraw + SM_PART);
    int*   rows  = (int*)  (smraw + SM_PART);   // overlays part (dead until Phase E)
    float* red   = (float*)(smraw + SM_PART);   // overlays part (epilogue only)
    float* urep  = (float*)(smraw + SM_SATT);   // overlays satt heads 0-1 (dead after E)
    float* sinv  = (float*)(smraw + SM_SINV);
    float* zb    = (float*)(smraw + SM_Z);
    float* lg    = (float*)(smraw + SM_LG);

    const int tid  = threadIdx.x;
    const int b    = blockIdx.x;
    const int warp = tid >> 5, lane = tid & 31;

    // ---- Phase A: stage att weights + gather indices ----
    for (int i = tid; i < 320; i += NT) aw[i] = att_w[i];
    if (tid < 5) ab[tid] = att_b[tid];
    for (int s = tid; s < S_; s += NT) rows[s] = x[b * S_ + s];
    __syncthreads();

    // ---- Phase B: gather 200 rows (float4), convert to half2, stage in SMEM ----
#pragma unroll 4
    for (int i = 0; i < 13; i++) {
        const int idx = i * NT + tid;
        if (idx < S_ * 16) {
            const int s = idx >> 4, q = idx & 15;
            const float4 v = __ldg((const float4*)(emb_table + (size_t)rows[s] * 64 + q * 4));
            *(half2*)(embh + s * 66 + q * 4)     = __floats2half2_rn(v.x, v.y);
            *(half2*)(embh + s * 66 + q * 4 + 2) = __floats2half2_rn(v.z, v.w);
        }
    }
    __syncthreads();

    // ---- Phase C: attention logits + tanh (one thread per s; float4 broadcast weights) ----
    if (tid < S_) {
        const int s = tid;
        const half2* e2 = (const half2*)(embh + s * 66);
        float a0 = ab[0], a1 = ab[1], a2 = ab[2], a3 = ab[3], a4 = ab[4];
#pragma unroll
        for (int j = 0; j < 16; j++) {
            const float2 ea = __half22float2(e2[2 * j]);
            const float2 eb = __half22float2(e2[2 * j + 1]);
            const float4 w0 = *(const float4*)(aw +        j * 4);
            const float4 w1 = *(const float4*)(aw +  64 +  j * 4);
            const float4 w2 = *(const float4*)(aw + 128 +  j * 4);
            const float4 w3 = *(const float4*)(aw + 192 +  j * 4);
            const float4 w4 = *(const float4*)(aw + 256 +  j * 4);
            a0 += ea.x*w0.x + ea.y*w0.y + eb.x*w0.z + eb.y*w0.w;
            a1 += ea.x*w1.x + ea.y*w1.y + eb.x*w1.z + eb.y*w1.w;
            a2 += ea.x*w2.x + ea.y*w2.y + eb.x*w2.z + eb.y*w2.w;
            a3 += ea.x*w3.x + ea.y*w3.y + eb.x*w3.z + eb.y*w3.w;
            a4 += ea.x*w4.x + ea.y*w4.y + eb.x*w4.z + eb.y*w4.w;
        }
        satt[      s] = tanhf(a0);
        satt[200 + s] = tanhf(a1);
        satt[400 + s] = tanhf(a2);
        satt[600 + s] = tanhf(a3);
        satt[800 + s] = tanhf(a4);
    }
    __syncthreads();

    // ---- Phase D: softmax over S per head (one warp per k; conflict-free rows) ----
    if (warp < 5) {
        float* row = satt + warp * 200;
        float m = -1e30f;
        for (int s = lane; s < S_; s += 32) m = fmaxf(m, row[s]);
#pragma unroll
        for (int o = 16; o; o >>= 1) m = fmaxf(m, __shfl_xor_sync(0xffffffffu, m, o));
        float sum = 0.f;
        for (int s = lane; s < S_; s += 32) {
            const float e = __expf(row[s] - m);
            row[s] = e;                       // unnormalized exp; 1/sum folded later
            sum += e;
        }
#pragma unroll
        for (int o = 16; o; o >>= 1) sum += __shfl_xor_sync(0xffffffffu, sum, o);
        if (lane == 0) sinv[warp] = 1.0f / sum;
    }
    __syncthreads();

    // ---- Pack pass: heads 0-3 exp scores -> half2 (exp in [0.135,1]: fp16-safe) ----
    if (tid < S_) {
        sc01[tid] = __floats2half2_rn(satt[tid],       satt[200 + tid]);
        sc23[tid] = __floats2half2_rn(satt[400 + tid], satt[600 + tid]);
    }
    __syncthreads();

    // ---- Phase E: user_rep partials; 4 warps, warp w does s = w, w+4, ... (50 iters) ----
    if (warp < 4) {
        float2 a0 = {0,0}, a1 = {0,0}, a2 = {0,0}, a3 = {0,0}, a4 = {0,0};
        const int dl = 2 * lane;
        for (int s = warp; s < S_; s += 4) {
            const float2 e   = __half22float2(*(const half2*)(embh + s * 66 + dl));
            const float2 s01 = __half22float2(sc01[s]);       // broadcast
            const float2 s23 = __half22float2(sc23[s]);       // broadcast
            const float  s4  = satt[800 + s];                 // broadcast
            a0.x += e.x * s01.x; a0.y += e.y * s01.x;
            a1.x += e.x * s01.y; a1.y += e.y * s01.y;
            a2.x += e.x * s23.x; a2.y += e.y * s23.x;
            a3.x += e.x * s23.y; a3.y += e.y * s23.y;
            a4.x += e.x * s4;    a4.y += e.y * s4;
        }
        half* pp = parth + warp * 320 + dl;
        *(half2*)(pp      ) = __floats2half2_rn(a0.x, a0.y);
        *(half2*)(pp +  64) = __floats2half2_rn(a1.x, a1.y);
        *(half2*)(pp + 128) = __floats2half2_rn(a2.x, a2.y);
        *(half2*)(pp + 192) = __floats2half2_rn(a3.x, a3.y);
        *(half2*)(pp + 256) = __floats2half2_rn(a4.x, a4.y);
    }
    __syncthreads();
    // combine the 4 warp partials -> urep (overlays satt, now dead)
    if (tid < 160) {
        float2 v = {0.f, 0.f};
#pragma unroll
        for (int w = 0; w < 4; w++) {
            const float2 t = __half22float2(*(const half2*)(parth + w * 320 + 2 * tid));
            v.x += t.x; v.y += t.y;
        }
        const float sc = sinv[(2 * tid) >> 6];
        urep[2 * tid]     = v.x * sc;
        urep[2 * tid + 1] = v.y * sc;
    }
    __syncthreads();

    // ---- Phase F: 18 logits ----
    if (tid < 18) {
        const int j = tid;
        const float* wp = (j < 2)  ? (W0 + j * 64)
                        : (j < 6)  ? (W1 + (j - 2)  * 64)
                        : (j < 10) ? (W2 + (j - 6)  * 64)
                        : (j < 12) ? (W3 + (j - 10) * 64)
                                   : (W4 + (j - 12) * 64);
        const int g = (j < 2) ? 0 : (j < 6) ? 1 : (j < 10) ? 2 : (j < 12) ? 3 : 4;
        const float* u = urep + g * 64;
        float z = 0.f;
#pragma unroll
        for (int i = 0; i < 16; i++) {
            const float4 uv = *(const float4*)(u + i * 4);
            const float4 wv = __ldg((const float4*)(wp + i * 4));
            z += uv.x*wv.x + uv.y*wv.y + uv.z*wv.z + uv.w*wv.w;
        }
        zb[j] = z;
    }
    __syncthreads();

    // ---- Phase G: per-group softmax + loss ----
    if (tid < 5) {
        const int cum[6] = {0, 2, 6, 10, 12, 18};
        const int g = tid, c0 = cum[g], n = cum[g + 1] - c0;
        float m = -1e30f;
        for (int j = 0; j < n; j++) m = fmaxf(m, zb[c0 + j]);
        float sum = 0.f;
        for (int j = 0; j < n; j++) sum += __expf(zb[c0 + j] - m);
        const float inv = 1.0f / sum;
        const float lse = m + __logf(sum);
        float lo = 0.f;
        for (int j = 0; j < n; j++) {
            const float zv = zb[c0 + j];
            out[b * 18 + c0 + j] = __expf(zv - m) * inv;
            lo -= y[b * 18 + c0 + j] * (zv - lse);   // y is one-hot
        }
        lg[g] = lo;
    }
    __syncthreads();

    // ---- Loss epilogue: last-CTA deterministic tree reduce (red overlays part) ----
    __shared__ int isLast;
    if (tid == 0) {
        g_loss[b] = lg[0] + lg[1] + lg[2] + lg[3] + lg[4];
        __threadfence();
        const unsigned old = atomicAdd(&g_cnt, 1u);
        isLast = (old == (unsigned)(B_ - 1));
    }
    __syncthreads();
    if (isLast) {
        float s = 0.f;
        for (int i = tid; i < B_; i += NT) s += g_loss[i];
        red[tid] = s;
        __syncthreads();
        for (int o = NT / 2; o; o >>= 1) {
            if (tid < o) red[tid] += red[tid + o];
            __syncthreads();
        }
        if (tid == 0) {
            out[B_ * 18] = red[0] * (1.0f / B_);
            g_cnt = 0u;                       // reset for next graph replay
        }
    }
}

extern "C" void kernel_launch(void* const* d_in, const int* in_sizes, int n_in,
                              void* d_out, int out_size)
{
    const int*   x   = (const int*)  d_in[0];
    const float* y   = (const float*)d_in[1];
    const float* emb = (const float*)d_in[2];
    const float* aw  = (const float*)d_in[3];
    const float* ab  = (const float*)d_in[4];
    const float* W0  = (const float*)d_in[5];
    const float* W1  = (const float*)d_in[6];
    const float* W2  = (const float*)d_in[7];
    const float* W3  = (const float*)d_in[8];
    const float* W4  = (const float*)d_in[9];
    float* out = (float*)d_out;

    tan_kernel<<<B_, NT, SM_BYTES>>>(x, y, emb, aw, ab, W0, W1, W2, W3, W4, out);
}